// round 15
// baseline (speedup 1.0000x reference)
#include <cuda_runtime.h>
#include <cstdint>

// ParallelTransport, R15: bf16x3 mma.sync + ldmatrix + 3-stage cp.async pipe.
//   M[b,i,j,:,:] = G[b,j,:,:] - L,  L = sum_d x[b,i,d]*A[b,j,d,:,:]
//   G[b,j,kl]    = sum_d x[b,j,d]*A[b,j,d,kl]   (f32, prep kernel)
//   L via mma.sync.m16n8k16 bf16, 3-pass split (h*h + h*l + l*h), fp32 accum.
//   A,x pre-split into bf16 hi/lo planes (__device__ scratch); A transposed
//   to [b][j][kl][d] so main staging is pure cp.async. Fragments via
//   ldmatrix.x4. Then 6-term Taylor exp per 8x8 (f32x2).

typedef unsigned long long u64;

#define SS 512
#define DD 512

// ---- global scratch ----
__device__ uint16_t g_Xh[4 * SS * DD];
__device__ uint16_t g_Xl[4 * SS * DD];
__device__ uint16_t g_Ah[(size_t)4 * SS * 64 * DD];
__device__ uint16_t g_Al[(size_t)4 * SS * 64 * DD];
__device__ float    g_G [4 * SS * 64];

// ---- main-kernel smem: 3 stages; per stage XH|XL|BH|BL, rows stride 80 B ----
#define ROW_B    80
#define SXL_OFF  10240                 // 128*80
#define SBH_OFF  20480
#define SBL_OFF  25600                 // +64*80
#define STAGE_B  30720
#define NSTAGE   3
#define DYN_SMEM (NSTAGE * STAGE_B)    // 92160
#define MST      68

// ---- f32x2 helpers ----
#define FMA2(D,A,B,C) asm("fma.rn.f32x2 %0,%1,%2,%3;" : "=l"(D) : "l"(A), "l"(B), "l"(C))
#define MUL2(D,A,B)   asm("mul.rn.f32x2 %0,%1,%2;"    : "=l"(D) : "l"(A), "l"(B))
#define ADD2(D,A,B)   asm("add.rn.f32x2 %0,%1,%2;"    : "=l"(D) : "l"(A), "l"(B))

static __device__ __forceinline__ u64 pk2(float a, float b) {
    u64 r; asm("mov.b64 %0,{%1,%2};" : "=l"(r) : "f"(a), "f"(b)); return r;
}
static __device__ __forceinline__ void upk2(float& a, float& b, u64 v) {
    asm("mov.b64 {%0,%1},%2;" : "=f"(a), "=f"(b) : "l"(v));
}
static __device__ __forceinline__ void split_bf(float v, uint16_t& h, uint16_t& l) {
    unsigned short hh;
    asm("cvt.rn.bf16.f32 %0, %1;" : "=h"(hh) : "f"(v));
    float hf = __uint_as_float((uint32_t)hh << 16);
    unsigned short ll;
    asm("cvt.rn.bf16.f32 %0, %1;" : "=h"(ll) : "f"(v - hf));
    h = hh; l = ll;
}
static __device__ __forceinline__ uint32_t smem_u32(const void* p) {
    uint32_t a;
    asm("{.reg .u64 t; cvta.to.shared.u64 t, %1; cvt.u32.u64 %0, t;}" : "=r"(a) : "l"(p));
    return a;
}
static __device__ __forceinline__ void cp16(uint32_t dst, const void* src) {
    asm volatile("cp.async.cg.shared.global [%0], [%1], 16;" :: "r"(dst), "l"(src) : "memory");
}
#define CP_COMMIT() asm volatile("cp.async.commit_group;" ::: "memory")
#define CP_WAIT2()  asm volatile("cp.async.wait_group 2;" ::: "memory")

#define LDSM4(R0,R1,R2,R3,ADDR) \
    asm volatile("ldmatrix.sync.aligned.m8n8.x4.shared.b16 {%0,%1,%2,%3}, [%4];" \
        : "=r"(R0), "=r"(R1), "=r"(R2), "=r"(R3) : "r"(ADDR))

static __device__ __forceinline__ void mma16(float c[4], const uint32_t a[4],
                                             uint32_t b0, uint32_t b1) {
    asm volatile(
        "mma.sync.aligned.m16n8k16.row.col.f32.bf16.bf16.f32 "
        "{%0,%1,%2,%3}, {%4,%5,%6,%7}, {%8,%9}, {%0,%1,%2,%3};"
        : "+f"(c[0]), "+f"(c[1]), "+f"(c[2]), "+f"(c[3])
        : "r"(a[0]), "r"(a[1]), "r"(a[2]), "r"(a[3]), "r"(b0), "r"(b1));
}

// ================= prep kernels (unchanged from R13) =================

__global__ void prep_x(const float* __restrict__ x)
{
    int f = blockIdx.x * 256 + threadIdx.x;
    float4 v = *(const float4*)(x + (size_t)f * 4);
    uint16_t h[4], l[4];
    split_bf(v.x, h[0], l[0]); split_bf(v.y, h[1], l[1]);
    split_bf(v.z, h[2], l[2]); split_bf(v.w, h[3], l[3]);
    uint2 hu, lu;
    hu.x = (uint32_t)h[0] | ((uint32_t)h[1] << 16);
    hu.y = (uint32_t)h[2] | ((uint32_t)h[3] << 16);
    lu.x = (uint32_t)l[0] | ((uint32_t)l[1] << 16);
    lu.y = (uint32_t)l[2] | ((uint32_t)l[3] << 16);
    *(uint2*)(g_Xh + (size_t)f * 4) = hu;
    *(uint2*)(g_Xl + (size_t)f * 4) = lu;
}

__global__ void prep_a(const float* __restrict__ x, const float* __restrict__ A)
{
    const int bj = blockIdx.x;
    const int tid = threadIdx.x;
    const int kl  = tid >> 2;
    const int sub = tid & 3;

    __shared__ float xrow[DD];
    __shared__ float sgp[64][5];

    xrow[tid]       = x[(size_t)bj * DD + tid];
    xrow[tid + 256] = x[(size_t)bj * DD + tid + 256];
    __syncthreads();

    const float* Ab = A + (size_t)bj * DD * 64;
    uint16_t* Oh = g_Ah + (size_t)bj * 64 * DD + (size_t)kl * DD;
    uint16_t* Ol = g_Al + (size_t)bj * 64 * DD + (size_t)kl * DD;

    float g = 0.0f;
#pragma unroll 1
    for (int c = 0; c < 8; c++) {
        const int d0 = c * 64 + sub * 16;
        uint16_t hb[16], lb[16];
#pragma unroll
        for (int i = 0; i < 16; i++) {
            float v = __ldg(Ab + (size_t)(d0 + i) * 64 + kl);
            g = fmaf(xrow[d0 + i], v, g);
            split_bf(v, hb[i], lb[i]);
        }
        uint4 u;
        u.x = (uint32_t)hb[0]  | ((uint32_t)hb[1]  << 16);
        u.y = (uint32_t)hb[2]  | ((uint32_t)hb[3]  << 16);
        u.z = (uint32_t)hb[4]  | ((uint32_t)hb[5]  << 16);
        u.w = (uint32_t)hb[6]  | ((uint32_t)hb[7]  << 16);
        *(uint4*)(Oh + d0) = u;
        u.x = (uint32_t)hb[8]  | ((uint32_t)hb[9]  << 16);
        u.y = (uint32_t)hb[10] | ((uint32_t)hb[11] << 16);
        u.z = (uint32_t)hb[12] | ((uint32_t)hb[13] << 16);
        u.w = (uint32_t)hb[14] | ((uint32_t)hb[15] << 16);
        *(uint4*)(Oh + d0 + 8) = u;
        u.x = (uint32_t)lb[0]  | ((uint32_t)lb[1]  << 16);
        u.y = (uint32_t)lb[2]  | ((uint32_t)lb[3]  << 16);
        u.z = (uint32_t)lb[4]  | ((uint32_t)lb[5]  << 16);
        u.w = (uint32_t)lb[6]  | ((uint32_t)lb[7]  << 16);
        *(uint4*)(Ol + d0) = u;
        u.x = (uint32_t)lb[8]  | ((uint32_t)lb[9]  << 16);
        u.y = (uint32_t)lb[10] | ((uint32_t)lb[11] << 16);
        u.z = (uint32_t)lb[12] | ((uint32_t)lb[13] << 16);
        u.w = (uint32_t)lb[14] | ((uint32_t)lb[15] << 16);
        *(uint4*)(Ol + d0 + 8) = u;
    }
    sgp[kl][sub] = g;
    __syncthreads();
    if (tid < 64)
        g_G[(size_t)bj * 64 + tid] =
            (sgp[tid][0] + sgp[tid][1]) + (sgp[tid][2] + sgp[tid][3]);
}

// ================= main kernel =================

__global__ __launch_bounds__(256, 2)
void pt_main(float* __restrict__ out)
{
    extern __shared__ __align__(16) char sm[];
    const uint32_t sb = smem_u32(sm);
    float (*Ms)[MST] = (float (*)[MST])sm;

    const int blk = blockIdx.x;
    const int it  = blk & 3;
    const int j   = (blk >> 2) & (SS - 1);
    const int b   = blk >> 11;
    const int i0  = it * 128;

    const int tid = threadIdx.x;
    const int wid = tid >> 5;
    const int lid = tid & 31;
    const int wm  = wid & 3;
    const int wn  = wid >> 2;
    const int g   = lid >> 2;
    const int t   = lid & 3;

    const uint16_t* Xh  = g_Xh + ((size_t)b * SS + i0) * DD;
    const uint16_t* Xl  = g_Xl + ((size_t)b * SS + i0) * DD;
    const uint16_t* Ahp = g_Ah + (size_t)(b * SS + j) * 64 * DD;
    const uint16_t* Alp = g_Al + (size_t)(b * SS + j) * 64 * DD;

    // per-lane ldmatrix offsets (within a stage region)
    const int sel = lid >> 3, rowin = lid & 7;
    uint32_t aoff[2], boff[2];
#pragma unroll
    for (int mf = 0; mf < 2; mf++)
        aoff[mf] = (uint32_t)((wm * 32 + mf * 16 + (sel & 1) * 8 + rowin) * ROW_B
                              + (sel >> 1) * 16);
#pragma unroll
    for (int pr = 0; pr < 2; pr++)
        boff[pr] = (uint32_t)((wn * 32 + (pr * 2 + (sel >> 1)) * 8 + rowin) * ROW_B
                              + (sel & 1) * 16);

    float C[2][4][4];
#pragma unroll
    for (int mf = 0; mf < 2; mf++)
#pragma unroll
        for (int nt = 0; nt < 4; nt++)
#pragma unroll
            for (int q = 0; q < 4; q++) C[mf][nt][q] = 0.0f;

    const int rr = tid >> 2;            // 0..63 (staging row)
    const int qq = tid & 3;             // 0..3

    // stage chunk `cc` into ring stage `st`
    auto stage = [&](int cc) {
        const int st = cc % NSTAGE;
        const uint32_t sB = sb + st * STAGE_B;
        const int dk = cc * 32;
        cp16(sB + rr * ROW_B + qq * 16,              Xh + (size_t)rr * DD + dk + qq * 8);
        cp16(sB + (rr + 64) * ROW_B + qq * 16,       Xh + (size_t)(rr + 64) * DD + dk + qq * 8);
        cp16(sB + SXL_OFF + rr * ROW_B + qq * 16,        Xl + (size_t)rr * DD + dk + qq * 8);
        cp16(sB + SXL_OFF + (rr + 64) * ROW_B + qq * 16, Xl + (size_t)(rr + 64) * DD + dk + qq * 8);
        cp16(sB + SBH_OFF + rr * ROW_B + qq * 16,    Ahp + (size_t)rr * DD + dk + qq * 8);
        cp16(sB + SBL_OFF + rr * ROW_B + qq * 16,    Alp + (size_t)rr * DD + dk + qq * 8);
    };

    stage(0); CP_COMMIT();
    stage(1); CP_COMMIT();

#pragma unroll 1
    for (int c = 0; c < 16; c++) {
        if (c + 2 < 16) stage(c + 2);
        CP_COMMIT();
        CP_WAIT2();
        __syncthreads();

        const uint32_t sB = sb + (c % NSTAGE) * STAGE_B;

#pragma unroll
        for (int ks = 0; ks < 2; ks++) {
            const uint32_t kb = ks * 32;
            uint32_t ah[2][4], al[2][4], bh[2][4], bl[2][4];
#pragma unroll
            for (int mf = 0; mf < 2; mf++) {
                LDSM4(ah[mf][0], ah[mf][1], ah[mf][2], ah[mf][3], sB + aoff[mf] + kb);
                LDSM4(al[mf][0], al[mf][1], al[mf][2], al[mf][3], sB + SXL_OFF + aoff[mf] + kb);
            }
#pragma unroll
            for (int pr = 0; pr < 2; pr++) {
                LDSM4(bh[pr][0], bh[pr][1], bh[pr][2], bh[pr][3], sB + SBH_OFF + boff[pr] + kb);
                LDSM4(bl[pr][0], bl[pr][1], bl[pr][2], bl[pr][3], sB + SBL_OFF + boff[pr] + kb);
            }
#pragma unroll
            for (int pr = 0; pr < 2; pr++)
#pragma unroll
                for (int sub = 0; sub < 2; sub++) {
                    const int nt = pr * 2 + sub;
                    uint32_t b0h = bh[pr][sub * 2], b1h = bh[pr][sub * 2 + 1];
                    uint32_t b0l = bl[pr][sub * 2], b1l = bl[pr][sub * 2 + 1];
#pragma unroll
                    for (int mf = 0; mf < 2; mf++) {
                        mma16(C[mf][nt], ah[mf], b0h, b1h);   // h*h
                        mma16(C[mf][nt], ah[mf], b0l, b1l);   // h*l
                        mma16(C[mf][nt], al[mf], b0h, b1h);   // l*h
                    }
                }
        }
        __syncthreads();
    }

    // ---- epilogue: Ms = G - L ----
    const float* Gp = g_G + (size_t)(b * SS + j) * 64;
#pragma unroll
    for (int nt = 0; nt < 4; nt++) {
        int c = wn * 32 + nt * 8 + 2 * t;
        float2 gv = *(const float2*)(Gp + c);
#pragma unroll
        for (int mf = 0; mf < 2; mf++) {
            int r = wm * 32 + mf * 16 + g;
            *(float2*)&Ms[r][c]     = make_float2(gv.x - C[mf][nt][0],
                                                  gv.y - C[mf][nt][1]);
            *(float2*)&Ms[r + 8][c] = make_float2(gv.x - C[mf][nt][2],
                                                  gv.y - C[mf][nt][3]);
        }
    }
    __syncthreads();

    // ---- Taylor: 8 lanes per 8x8 matrix, f32x2, 4 passes ----
    const int r     = tid & 7;
    const int mbase = tid >> 3;
    const float invn[7] = {0.f, 1.f, 0.5f, 1.f / 3.f, 0.25f, 0.2f, 1.f / 6.f};

#pragma unroll 1
    for (int p = 0; p < 4; p++) {
        const int m = p * 32 + mbase;

        u64 Mg[8][4];
#pragma unroll
        for (int k = 0; k < 8; k++) {
            ulonglong2 t0 = *(const ulonglong2*)&Ms[m][k * 8];
            ulonglong2 t1 = *(const ulonglong2*)&Ms[m][k * 8 + 4];
            Mg[k][0] = t0.x; Mg[k][1] = t0.y; Mg[k][2] = t1.x; Mg[k][3] = t1.y;
        }
        u64 P[4], res[4];
        {
            ulonglong2 t0 = *(const ulonglong2*)&Ms[m][r * 8];
            ulonglong2 t1 = *(const ulonglong2*)&Ms[m][r * 8 + 4];
            P[0] = t0.x; P[1] = t0.y; P[2] = t1.x; P[3] = t1.y;
        }
#pragma unroll
        for (int c2 = 0; c2 < 4; c2++) res[c2] = P[c2];

#pragma unroll
        for (int n = 2; n <= 6; n++) {
            float ps[8];
#pragma unroll
            for (int c2 = 0; c2 < 4; c2++) upk2(ps[2 * c2], ps[2 * c2 + 1], P[c2]);
            u64 nw[4] = {0ULL, 0ULL, 0ULL, 0ULL};
#pragma unroll
            for (int k = 0; k < 8; k++) {
                u64 s2 = pk2(ps[k], ps[k]);
#pragma unroll
                for (int c2 = 0; c2 < 4; c2++)
                    FMA2(nw[c2], s2, Mg[k][c2], nw[c2]);
            }
            uint32_t ub = __float_as_uint(invn[n]);
            u64 sc2 = (u64)ub | ((u64)ub << 32);
#pragma unroll
            for (int c2 = 0; c2 < 4; c2++) {
                MUL2(nw[c2], nw[c2], sc2);
                P[c2] = nw[c2];
                ADD2(res[c2], res[c2], nw[c2]);
            }
        }

        float fr[8];
#pragma unroll
        for (int c2 = 0; c2 < 4; c2++) upk2(fr[2 * c2], fr[2 * c2 + 1], res[c2]);
#pragma unroll
        for (int cc = 0; cc < 8; cc++) fr[cc] += (cc == r) ? 1.0f : 0.0f;

        size_t off = (((size_t)b * SS + (i0 + m)) * SS + j) * 64 + (size_t)r * 8;
        *(float4*)(out + off)     = make_float4(fr[0], fr[1], fr[2], fr[3]);
        *(float4*)(out + off + 4) = make_float4(fr[4], fr[5], fr[6], fr[7]);
    }
}

// ================= launcher =================

extern "C" void kernel_launch(void* const* d_in, const int* in_sizes, int n_in,
                              void* d_out, int out_size)
{
    const float* x = (const float*)d_in[0];   // [4,512,512]
    const float* A = (const float*)d_in[1];   // [4,512,512,8,8]
    float* out = (float*)d_out;               // [4,512,512,8,8]
    (void)in_sizes; (void)n_in; (void)out_size;

    cudaFuncSetAttribute(pt_main, cudaFuncAttributeMaxDynamicSharedMemorySize, DYN_SMEM);

    prep_x<<<1024, 256>>>(x);
    prep_a<<<4 * SS, 256>>>(x, A);
    pt_main<<<4 * SS * 4, 256, DYN_SMEM>>>(out);
}

// round 16
// speedup vs baseline: 1.0002x; 1.0002x over previous
#include <cuda_runtime.h>
#include <cstdint>

// ParallelTransport, R15: bf16x3 mma.sync + ldmatrix + 3-stage cp.async pipe.
//   M[b,i,j,:,:] = G[b,j,:,:] - L,  L = sum_d x[b,i,d]*A[b,j,d,:,:]
//   G[b,j,kl]    = sum_d x[b,j,d]*A[b,j,d,kl]   (f32, prep kernel)
//   L via mma.sync.m16n8k16 bf16, 3-pass split (h*h + h*l + l*h), fp32 accum.
//   A,x pre-split into bf16 hi/lo planes (__device__ scratch); A transposed
//   to [b][j][kl][d] so main staging is pure cp.async. Fragments via
//   ldmatrix.x4. Then 6-term Taylor exp per 8x8 (f32x2).

typedef unsigned long long u64;

#define SS 512
#define DD 512

// ---- global scratch ----
__device__ uint16_t g_Xh[4 * SS * DD];
__device__ uint16_t g_Xl[4 * SS * DD];
__device__ uint16_t g_Ah[(size_t)4 * SS * 64 * DD];
__device__ uint16_t g_Al[(size_t)4 * SS * 64 * DD];
__device__ float    g_G [4 * SS * 64];

// ---- main-kernel smem: 3 stages; per stage XH|XL|BH|BL, rows stride 80 B ----
#define ROW_B    80
#define SXL_OFF  10240                 // 128*80
#define SBH_OFF  20480
#define SBL_OFF  25600                 // +64*80
#define STAGE_B  30720
#define NSTAGE   3
#define DYN_SMEM (NSTAGE * STAGE_B)    // 92160
#define MST      68

// ---- f32x2 helpers ----
#define FMA2(D,A,B,C) asm("fma.rn.f32x2 %0,%1,%2,%3;" : "=l"(D) : "l"(A), "l"(B), "l"(C))
#define MUL2(D,A,B)   asm("mul.rn.f32x2 %0,%1,%2;"    : "=l"(D) : "l"(A), "l"(B))
#define ADD2(D,A,B)   asm("add.rn.f32x2 %0,%1,%2;"    : "=l"(D) : "l"(A), "l"(B))

static __device__ __forceinline__ u64 pk2(float a, float b) {
    u64 r; asm("mov.b64 %0,{%1,%2};" : "=l"(r) : "f"(a), "f"(b)); return r;
}
static __device__ __forceinline__ void upk2(float& a, float& b, u64 v) {
    asm("mov.b64 {%0,%1},%2;" : "=f"(a), "=f"(b) : "l"(v));
}
static __device__ __forceinline__ void split_bf(float v, uint16_t& h, uint16_t& l) {
    unsigned short hh;
    asm("cvt.rn.bf16.f32 %0, %1;" : "=h"(hh) : "f"(v));
    float hf = __uint_as_float((uint32_t)hh << 16);
    unsigned short ll;
    asm("cvt.rn.bf16.f32 %0, %1;" : "=h"(ll) : "f"(v - hf));
    h = hh; l = ll;
}
static __device__ __forceinline__ uint32_t smem_u32(const void* p) {
    uint32_t a;
    asm("{.reg .u64 t; cvta.to.shared.u64 t, %1; cvt.u32.u64 %0, t;}" : "=r"(a) : "l"(p));
    return a;
}
static __device__ __forceinline__ void cp16(uint32_t dst, const void* src) {
    asm volatile("cp.async.cg.shared.global [%0], [%1], 16;" :: "r"(dst), "l"(src) : "memory");
}
#define CP_COMMIT() asm volatile("cp.async.commit_group;" ::: "memory")
#define CP_WAIT2()  asm volatile("cp.async.wait_group 2;" ::: "memory")

#define LDSM4(R0,R1,R2,R3,ADDR) \
    asm volatile("ldmatrix.sync.aligned.m8n8.x4.shared.b16 {%0,%1,%2,%3}, [%4];" \
        : "=r"(R0), "=r"(R1), "=r"(R2), "=r"(R3) : "r"(ADDR))

static __device__ __forceinline__ void mma16(float c[4], const uint32_t a[4],
                                             uint32_t b0, uint32_t b1) {
    asm volatile(
        "mma.sync.aligned.m16n8k16.row.col.f32.bf16.bf16.f32 "
        "{%0,%1,%2,%3}, {%4,%5,%6,%7}, {%8,%9}, {%0,%1,%2,%3};"
        : "+f"(c[0]), "+f"(c[1]), "+f"(c[2]), "+f"(c[3])
        : "r"(a[0]), "r"(a[1]), "r"(a[2]), "r"(a[3]), "r"(b0), "r"(b1));
}

// ================= prep kernels (unchanged from R13) =================

__global__ void prep_x(const float* __restrict__ x)
{
    int f = blockIdx.x * 256 + threadIdx.x;
    float4 v = *(const float4*)(x + (size_t)f * 4);
    uint16_t h[4], l[4];
    split_bf(v.x, h[0], l[0]); split_bf(v.y, h[1], l[1]);
    split_bf(v.z, h[2], l[2]); split_bf(v.w, h[3], l[3]);
    uint2 hu, lu;
    hu.x = (uint32_t)h[0] | ((uint32_t)h[1] << 16);
    hu.y = (uint32_t)h[2] | ((uint32_t)h[3] << 16);
    lu.x = (uint32_t)l[0] | ((uint32_t)l[1] << 16);
    lu.y = (uint32_t)l[2] | ((uint32_t)l[3] << 16);
    *(uint2*)(g_Xh + (size_t)f * 4) = hu;
    *(uint2*)(g_Xl + (size_t)f * 4) = lu;
}

__global__ void prep_a(const float* __restrict__ x, const float* __restrict__ A)
{
    const int bj = blockIdx.x;
    const int tid = threadIdx.x;
    const int kl  = tid >> 2;
    const int sub = tid & 3;

    __shared__ float xrow[DD];
    __shared__ float sgp[64][5];

    xrow[tid]       = x[(size_t)bj * DD + tid];
    xrow[tid + 256] = x[(size_t)bj * DD + tid + 256];
    __syncthreads();

    const float* Ab = A + (size_t)bj * DD * 64;
    uint16_t* Oh = g_Ah + (size_t)bj * 64 * DD + (size_t)kl * DD;
    uint16_t* Ol = g_Al + (size_t)bj * 64 * DD + (size_t)kl * DD;

    float g = 0.0f;
#pragma unroll 1
    for (int c = 0; c < 8; c++) {
        const int d0 = c * 64 + sub * 16;
        uint16_t hb[16], lb[16];
#pragma unroll
        for (int i = 0; i < 16; i++) {
            float v = __ldg(Ab + (size_t)(d0 + i) * 64 + kl);
            g = fmaf(xrow[d0 + i], v, g);
            split_bf(v, hb[i], lb[i]);
        }
        uint4 u;
        u.x = (uint32_t)hb[0]  | ((uint32_t)hb[1]  << 16);
        u.y = (uint32_t)hb[2]  | ((uint32_t)hb[3]  << 16);
        u.z = (uint32_t)hb[4]  | ((uint32_t)hb[5]  << 16);
        u.w = (uint32_t)hb[6]  | ((uint32_t)hb[7]  << 16);
        *(uint4*)(Oh + d0) = u;
        u.x = (uint32_t)hb[8]  | ((uint32_t)hb[9]  << 16);
        u.y = (uint32_t)hb[10] | ((uint32_t)hb[11] << 16);
        u.z = (uint32_t)hb[12] | ((uint32_t)hb[13] << 16);
        u.w = (uint32_t)hb[14] | ((uint32_t)hb[15] << 16);
        *(uint4*)(Oh + d0 + 8) = u;
        u.x = (uint32_t)lb[0]  | ((uint32_t)lb[1]  << 16);
        u.y = (uint32_t)lb[2]  | ((uint32_t)lb[3]  << 16);
        u.z = (uint32_t)lb[4]  | ((uint32_t)lb[5]  << 16);
        u.w = (uint32_t)lb[6]  | ((uint32_t)lb[7]  << 16);
        *(uint4*)(Ol + d0) = u;
        u.x = (uint32_t)lb[8]  | ((uint32_t)lb[9]  << 16);
        u.y = (uint32_t)lb[10] | ((uint32_t)lb[11] << 16);
        u.z = (uint32_t)lb[12] | ((uint32_t)lb[13] << 16);
        u.w = (uint32_t)lb[14] | ((uint32_t)lb[15] << 16);
        *(uint4*)(Ol + d0 + 8) = u;
    }
    sgp[kl][sub] = g;
    __syncthreads();
    if (tid < 64)
        g_G[(size_t)bj * 64 + tid] =
            (sgp[tid][0] + sgp[tid][1]) + (sgp[tid][2] + sgp[tid][3]);
}

// ================= main kernel =================

__global__ __launch_bounds__(256, 2)
void pt_main(float* __restrict__ out)
{
    extern __shared__ __align__(16) char sm[];
    const uint32_t sb = smem_u32(sm);
    float (*Ms)[MST] = (float (*)[MST])sm;

    const int blk = blockIdx.x;
    const int it  = blk & 3;
    const int j   = (blk >> 2) & (SS - 1);
    const int b   = blk >> 11;
    const int i0  = it * 128;

    const int tid = threadIdx.x;
    const int wid = tid >> 5;
    const int lid = tid & 31;
    const int wm  = wid & 3;
    const int wn  = wid >> 2;
    const int g   = lid >> 2;
    const int t   = lid & 3;

    const uint16_t* Xh  = g_Xh + ((size_t)b * SS + i0) * DD;
    const uint16_t* Xl  = g_Xl + ((size_t)b * SS + i0) * DD;
    const uint16_t* Ahp = g_Ah + (size_t)(b * SS + j) * 64 * DD;
    const uint16_t* Alp = g_Al + (size_t)(b * SS + j) * 64 * DD;

    // per-lane ldmatrix offsets (within a stage region)
    const int sel = lid >> 3, rowin = lid & 7;
    uint32_t aoff[2], boff[2];
#pragma unroll
    for (int mf = 0; mf < 2; mf++)
        aoff[mf] = (uint32_t)((wm * 32 + mf * 16 + (sel & 1) * 8 + rowin) * ROW_B
                              + (sel >> 1) * 16);
#pragma unroll
    for (int pr = 0; pr < 2; pr++)
        boff[pr] = (uint32_t)((wn * 32 + (pr * 2 + (sel >> 1)) * 8 + rowin) * ROW_B
                              + (sel & 1) * 16);

    float C[2][4][4];
#pragma unroll
    for (int mf = 0; mf < 2; mf++)
#pragma unroll
        for (int nt = 0; nt < 4; nt++)
#pragma unroll
            for (int q = 0; q < 4; q++) C[mf][nt][q] = 0.0f;

    const int rr = tid >> 2;            // 0..63 (staging row)
    const int qq = tid & 3;             // 0..3

    // stage chunk `cc` into ring stage `st`
    auto stage = [&](int cc) {
        const int st = cc % NSTAGE;
        const uint32_t sB = sb + st * STAGE_B;
        const int dk = cc * 32;
        cp16(sB + rr * ROW_B + qq * 16,              Xh + (size_t)rr * DD + dk + qq * 8);
        cp16(sB + (rr + 64) * ROW_B + qq * 16,       Xh + (size_t)(rr + 64) * DD + dk + qq * 8);
        cp16(sB + SXL_OFF + rr * ROW_B + qq * 16,        Xl + (size_t)rr * DD + dk + qq * 8);
        cp16(sB + SXL_OFF + (rr + 64) * ROW_B + qq * 16, Xl + (size_t)(rr + 64) * DD + dk + qq * 8);
        cp16(sB + SBH_OFF + rr * ROW_B + qq * 16,    Ahp + (size_t)rr * DD + dk + qq * 8);
        cp16(sB + SBL_OFF + rr * ROW_B + qq * 16,    Alp + (size_t)rr * DD + dk + qq * 8);
    };

    stage(0); CP_COMMIT();
    stage(1); CP_COMMIT();

#pragma unroll 1
    for (int c = 0; c < 16; c++) {
        if (c + 2 < 16) stage(c + 2);
        CP_COMMIT();
        CP_WAIT2();
        __syncthreads();

        const uint32_t sB = sb + (c % NSTAGE) * STAGE_B;

#pragma unroll
        for (int ks = 0; ks < 2; ks++) {
            const uint32_t kb = ks * 32;
            uint32_t ah[2][4], al[2][4], bh[2][4], bl[2][4];
#pragma unroll
            for (int mf = 0; mf < 2; mf++) {
                LDSM4(ah[mf][0], ah[mf][1], ah[mf][2], ah[mf][3], sB + aoff[mf] + kb);
                LDSM4(al[mf][0], al[mf][1], al[mf][2], al[mf][3], sB + SXL_OFF + aoff[mf] + kb);
            }
#pragma unroll
            for (int pr = 0; pr < 2; pr++) {
                LDSM4(bh[pr][0], bh[pr][1], bh[pr][2], bh[pr][3], sB + SBH_OFF + boff[pr] + kb);
                LDSM4(bl[pr][0], bl[pr][1], bl[pr][2], bl[pr][3], sB + SBL_OFF + boff[pr] + kb);
            }
#pragma unroll
            for (int pr = 0; pr < 2; pr++)
#pragma unroll
                for (int sub = 0; sub < 2; sub++) {
                    const int nt = pr * 2 + sub;
                    uint32_t b0h = bh[pr][sub * 2], b1h = bh[pr][sub * 2 + 1];
                    uint32_t b0l = bl[pr][sub * 2], b1l = bl[pr][sub * 2 + 1];
#pragma unroll
                    for (int mf = 0; mf < 2; mf++) {
                        mma16(C[mf][nt], ah[mf], b0h, b1h);   // h*h
                        mma16(C[mf][nt], ah[mf], b0l, b1l);   // h*l
                        mma16(C[mf][nt], al[mf], b0h, b1h);   // l*h
                    }
                }
        }
        __syncthreads();
    }

    // ---- epilogue: Ms = G - L ----
    const float* Gp = g_G + (size_t)(b * SS + j) * 64;
#pragma unroll
    for (int nt = 0; nt < 4; nt++) {
        int c = wn * 32 + nt * 8 + 2 * t;
        float2 gv = *(const float2*)(Gp + c);
#pragma unroll
        for (int mf = 0; mf < 2; mf++) {
            int r = wm * 32 + mf * 16 + g;
            *(float2*)&Ms[r][c]     = make_float2(gv.x - C[mf][nt][0],
                                                  gv.y - C[mf][nt][1]);
            *(float2*)&Ms[r + 8][c] = make_float2(gv.x - C[mf][nt][2],
                                                  gv.y - C[mf][nt][3]);
        }
    }
    __syncthreads();

    // ---- Taylor: 8 lanes per 8x8 matrix, f32x2, 4 passes ----
    const int r     = tid & 7;
    const int mbase = tid >> 3;
    const float invn[7] = {0.f, 1.f, 0.5f, 1.f / 3.f, 0.25f, 0.2f, 1.f / 6.f};

#pragma unroll 1
    for (int p = 0; p < 4; p++) {
        const int m = p * 32 + mbase;

        u64 Mg[8][4];
#pragma unroll
        for (int k = 0; k < 8; k++) {
            ulonglong2 t0 = *(const ulonglong2*)&Ms[m][k * 8];
            ulonglong2 t1 = *(const ulonglong2*)&Ms[m][k * 8 + 4];
            Mg[k][0] = t0.x; Mg[k][1] = t0.y; Mg[k][2] = t1.x; Mg[k][3] = t1.y;
        }
        u64 P[4], res[4];
        {
            ulonglong2 t0 = *(const ulonglong2*)&Ms[m][r * 8];
            ulonglong2 t1 = *(const ulonglong2*)&Ms[m][r * 8 + 4];
            P[0] = t0.x; P[1] = t0.y; P[2] = t1.x; P[3] = t1.y;
        }
#pragma unroll
        for (int c2 = 0; c2 < 4; c2++) res[c2] = P[c2];

#pragma unroll
        for (int n = 2; n <= 6; n++) {
            float ps[8];
#pragma unroll
            for (int c2 = 0; c2 < 4; c2++) upk2(ps[2 * c2], ps[2 * c2 + 1], P[c2]);
            u64 nw[4] = {0ULL, 0ULL, 0ULL, 0ULL};
#pragma unroll
            for (int k = 0; k < 8; k++) {
                u64 s2 = pk2(ps[k], ps[k]);
#pragma unroll
                for (int c2 = 0; c2 < 4; c2++)
                    FMA2(nw[c2], s2, Mg[k][c2], nw[c2]);
            }
            uint32_t ub = __float_as_uint(invn[n]);
            u64 sc2 = (u64)ub | ((u64)ub << 32);
#pragma unroll
            for (int c2 = 0; c2 < 4; c2++) {
                MUL2(nw[c2], nw[c2], sc2);
                P[c2] = nw[c2];
                ADD2(res[c2], res[c2], nw[c2]);
            }
        }

        float fr[8];
#pragma unroll
        for (int c2 = 0; c2 < 4; c2++) upk2(fr[2 * c2], fr[2 * c2 + 1], res[c2]);
#pragma unroll
        for (int cc = 0; cc < 8; cc++) fr[cc] += (cc == r) ? 1.0f : 0.0f;

        size_t off = (((size_t)b * SS + (i0 + m)) * SS + j) * 64 + (size_t)r * 8;
        *(float4*)(out + off)     = make_float4(fr[0], fr[1], fr[2], fr[3]);
        *(float4*)(out + off + 4) = make_float4(fr[4], fr[5], fr[6], fr[7]);
    }
}

// ================= launcher =================

extern "C" void kernel_launch(void* const* d_in, const int* in_sizes, int n_in,
                              void* d_out, int out_size)
{
    const float* x = (const float*)d_in[0];   // [4,512,512]
    const float* A = (const float*)d_in[1];   // [4,512,512,8,8]
    float* out = (float*)d_out;               // [4,512,512,8,8]
    (void)in_sizes; (void)n_in; (void)out_size;

    cudaFuncSetAttribute(pt_main, cudaFuncAttributeMaxDynamicSharedMemorySize, DYN_SMEM);

    prep_x<<<1024, 256>>>(x);
    prep_a<<<4 * SS, 256>>>(x, A);
    pt_main<<<4 * SS * 4, 256, DYN_SMEM>>>(out);
}